// round 8
// baseline (speedup 1.0000x reference)
#include <cuda_runtime.h>
#include <cstdint>

// CorrelationMSELoss — B=8192 rows, L=1024 labels, single fused kernel.
// out = mean((pred-label)^2) + sum_rows(row_loss)
// Whole row per warp held in registers: 8 x 256-bit asm-volatile loads
// front-batched so ptxas cannot collapse the MLP.

static constexpr int B_ROWS = 8192;
static constexpr int L_COLS = 1024;
static constexpr int WARPS_PER_BLOCK = 8;
static constexpr int THREADS = WARPS_PER_BLOCK * 32;   // 256
static constexpr int GRID = B_ROWS / WARPS_PER_BLOCK;  // 1024 blocks

__device__ float g_part_mse[GRID];
__device__ float g_part_loss[GRID];
__device__ unsigned int g_count = 0;  // reset by last block each launch

__device__ __forceinline__ float ex2_approx(float x) {
    float r;
    asm("ex2.approx.ftz.f32 %0, %1;" : "=f"(r) : "f"(x));
    return r;
}

// 256-bit non-coherent load; volatile => issue order preserved, regs live.
__device__ __forceinline__ void ldg256(const void* p, uint64_t r[4]) {
    asm volatile("ld.global.nc.v4.b64 {%0,%1,%2,%3}, [%4];"
                 : "=l"(r[0]), "=l"(r[1]), "=l"(r[2]), "=l"(r[3])
                 : "l"(p));
}

__device__ __forceinline__ void accum8(const uint64_t pr[4], const uint64_t lr[4],
                                       float& mse, float& spos, float& stot, float& none) {
    constexpr float L2E = 1.4426950408889634f;  // log2(e)
#pragma unroll
    for (int j = 0; j < 4; ++j) {
        float pv0 = __uint_as_float((unsigned)(pr[j] & 0xffffffffu));
        float pv1 = __uint_as_float((unsigned)(pr[j] >> 32));
        float lv0 = __uint_as_float((unsigned)(lr[j] & 0xffffffffu));
        float lv1 = __uint_as_float((unsigned)(lr[j] >> 32));
        float pv[2] = {pv0, pv1}, lv[2] = {lv0, lv1};
#pragma unroll
        for (int h = 0; h < 2; ++h) {
            float p = pv[h], l = lv[h];
            float d = p - l;
            mse = fmaf(d, d, mse);
            float t = p * L2E;
            float arg = fmaf(l, -2.f * t, t);  // +t for l=0, -t for l=1
            float e = ex2_approx(arg);
            stot += e;
            spos = fmaf(l, e, spos);
            none += l;  // exact integer count
        }
    }
}

__global__ __launch_bounds__(THREADS) void k_fused(const float* __restrict__ pred,
                                                   const float* __restrict__ label,
                                                   float* __restrict__ out) {
    const int lane = threadIdx.x & 31;
    const int warp = threadIdx.x >> 5;
    const int row = blockIdx.x * WARPS_PER_BLOCK + warp;

    // each lane owns 32 consecutive floats (128 B) of the row -> 4 x 32B loads per array
    const char* pb = reinterpret_cast<const char*>(pred) + (long)row * (L_COLS * 4) + lane * 128;
    const char* lb = reinterpret_cast<const char*>(label) + (long)row * (L_COLS * 4) + lane * 128;

    // front-batch ALL 8 loads (asm volatile: order fixed, MLP_p1 = 8)
    uint64_t pr0[4], pr1[4], pr2[4], pr3[4];
    uint64_t lr0[4], lr1[4], lr2[4], lr3[4];
    ldg256(pb + 0,  pr0);
    ldg256(pb + 32, pr1);
    ldg256(pb + 64, pr2);
    ldg256(pb + 96, pr3);
    ldg256(lb + 0,  lr0);
    ldg256(lb + 32, lr1);
    ldg256(lb + 64, lr2);
    ldg256(lb + 96, lr3);

    float mse = 0.f, spos = 0.f, stot = 0.f, none = 0.f;
    accum8(pr0, lr0, mse, spos, stot, none);
    accum8(pr1, lr1, mse, spos, stot, none);
    accum8(pr2, lr2, mse, spos, stot, none);
    accum8(pr3, lr3, mse, spos, stot, none);

    // warp reduction (warp owns one row)
#pragma unroll
    for (int off = 16; off; off >>= 1) {
        mse  += __shfl_xor_sync(0xffffffffu, mse, off);
        spos += __shfl_xor_sync(0xffffffffu, spos, off);
        stot += __shfl_xor_sync(0xffffffffu, stot, off);
        none += __shfl_xor_sync(0xffffffffu, none, off);
    }

    __shared__ float s_mse[WARPS_PER_BLOCK];
    __shared__ float s_loss[WARPS_PER_BLOCK];
    __shared__ bool s_last;

    if (lane == 0) {
        float n1 = none;
        float n0 = (float)L_COLS - none;
        float sneg = stot - spos;
        float loss;
        if (n1 == 0.f) {
            loss = sneg * 0.36787944117144233f / fmaxf(n0, 1.f);  // e^{-1}*s_neg/n0
        } else if (n0 == 0.f) {
            loss = spos / n1;
        } else {
            loss = (spos * sneg) / (n1 * n0);
        }
        s_mse[warp] = mse;
        s_loss[warp] = loss;
    }
    __syncthreads();

    if (warp == 0 && lane < WARPS_PER_BLOCK) {
        float bm = s_mse[lane];
        float bl = s_loss[lane];
#pragma unroll
        for (int off = 4; off; off >>= 1) {
            bm += __shfl_xor_sync(0x000000ffu, bm, off);
            bl += __shfl_xor_sync(0x000000ffu, bl, off);
        }
        if (lane == 0) {
            g_part_mse[blockIdx.x] = bm;
            g_part_loss[blockIdx.x] = bl;
        }
    }

    // last-block final reduction (threadfence-reduction pattern)
    if (threadIdx.x == 0) {
        __threadfence();
        unsigned int prev = atomicAdd(&g_count, 1u);
        s_last = (prev == (unsigned)gridDim.x - 1u);
    }
    __syncthreads();

    if (s_last) {
        // 1024 partials per array; 256 threads -> one float4 each
        const float4* pm4 = reinterpret_cast<const float4*>(g_part_mse);
        const float4* pl4 = reinterpret_cast<const float4*>(g_part_loss);
        float4 vm = pm4[threadIdx.x];
        float4 vl = pl4[threadIdx.x];
        double dm = (double)vm.x + (double)vm.y + (double)vm.z + (double)vm.w;
        double dl = (double)vl.x + (double)vl.y + (double)vl.z + (double)vl.w;
#pragma unroll
        for (int off = 16; off; off >>= 1) {
            dm += __shfl_xor_sync(0xffffffffu, dm, off);
            dl += __shfl_xor_sync(0xffffffffu, dl, off);
        }
        __shared__ double sd_m[WARPS_PER_BLOCK];
        __shared__ double sd_l[WARPS_PER_BLOCK];
        if (lane == 0) {
            sd_m[warp] = dm;
            sd_l[warp] = dl;
        }
        __syncthreads();
        if (threadIdx.x == 0) {
            double tm = 0.0, tl = 0.0;
#pragma unroll
            for (int w = 0; w < WARPS_PER_BLOCK; ++w) {
                tm += sd_m[w];
                tl += sd_l[w];
            }
            out[0] = (float)(tm * (1.0 / ((double)B_ROWS * (double)L_COLS)) + tl);
            g_count = 0;  // reset for next graph replay
        }
    }
}

extern "C" void kernel_launch(void* const* d_in, const int* in_sizes, int n_in,
                              void* d_out, int out_size) {
    const float* pred  = (const float*)d_in[0];
    const float* label = (const float*)d_in[1];
    float* out = (float*)d_out;
    k_fused<<<GRID, THREADS>>>(pred, label, out);
}

// round 9
// speedup vs baseline: 1.2691x; 1.2691x over previous
#include <cuda_runtime.h>

// CorrelationMSELoss — B=8192 rows, L=1024 labels, single fused kernel.
// out = mean((pred-label)^2) + sum_rows(row_loss)
// MLP fix: 8 asm-volatile 128-bit loads batched per stage + reg budget 64
// (launch_bounds minBlocks=4) so ptxas can neither interleave nor spill.

static constexpr int B_ROWS = 8192;
static constexpr int L_COLS = 1024;
static constexpr int WARPS_PER_BLOCK = 8;
static constexpr int THREADS = WARPS_PER_BLOCK * 32;   // 256
static constexpr int GRID = B_ROWS / WARPS_PER_BLOCK;  // 1024 blocks

__device__ float g_part_mse[GRID];
__device__ float g_part_loss[GRID];
__device__ unsigned int g_count = 0;  // reset by last block each launch

__device__ __forceinline__ float ex2_approx(float x) {
    float r;
    asm("ex2.approx.ftz.f32 %0, %1;" : "=f"(r) : "f"(x));
    return r;
}

// 128-bit non-coherent load, asm volatile: issue order preserved by ptxas.
__device__ __forceinline__ float4 ldg128(const float4* p) {
    float4 v;
    asm volatile("ld.global.nc.v4.f32 {%0,%1,%2,%3}, [%4];"
                 : "=f"(v.x), "=f"(v.y), "=f"(v.z), "=f"(v.w)
                 : "l"(p));
    return v;
}

__device__ __forceinline__ void accum_chunk(float4 p, float4 l, float& mse,
                                            float& spos, float& stot, float& none) {
    constexpr float L2E = 1.4426950408889634f;  // log2(e)
    float pe[4] = {p.x, p.y, p.z, p.w};
    float le[4] = {l.x, l.y, l.z, l.w};
#pragma unroll
    for (int j = 0; j < 4; ++j) {
        float pv = pe[j], lv = le[j];
        float d = pv - lv;
        mse = fmaf(d, d, mse);
        float t = pv * L2E;
        float arg = fmaf(lv, -2.f * t, t);  // +t for lv=0, -t for lv=1
        float e = ex2_approx(arg);
        stot += e;
        spos = fmaf(lv, e, spos);
        none += lv;  // exact integer count
    }
}

__global__ __launch_bounds__(THREADS, 4) void k_fused(const float* __restrict__ pred,
                                                      const float* __restrict__ label,
                                                      float* __restrict__ out) {
    const int lane = threadIdx.x & 31;
    const int warp = threadIdx.x >> 5;
    const int row = blockIdx.x * WARPS_PER_BLOCK + warp;

    const float4* p4 = reinterpret_cast<const float4*>(pred) + (long)row * (L_COLS / 4) + lane;
    const float4* l4 = reinterpret_cast<const float4*>(label) + (long)row * (L_COLS / 4) + lane;

    float mse = 0.f, spos = 0.f, stot = 0.f, none = 0.f;

    // 2 stages; each stage front-batches 8 asm-volatile LDG.128 (32 data regs)
#pragma unroll
    for (int s = 0; s < 2; ++s) {
        float4 pr0 = ldg128(p4 + (s * 4 + 0) * 32);
        float4 pr1 = ldg128(p4 + (s * 4 + 1) * 32);
        float4 pr2 = ldg128(p4 + (s * 4 + 2) * 32);
        float4 pr3 = ldg128(p4 + (s * 4 + 3) * 32);
        float4 lr0 = ldg128(l4 + (s * 4 + 0) * 32);
        float4 lr1 = ldg128(l4 + (s * 4 + 1) * 32);
        float4 lr2 = ldg128(l4 + (s * 4 + 2) * 32);
        float4 lr3 = ldg128(l4 + (s * 4 + 3) * 32);
        accum_chunk(pr0, lr0, mse, spos, stot, none);
        accum_chunk(pr1, lr1, mse, spos, stot, none);
        accum_chunk(pr2, lr2, mse, spos, stot, none);
        accum_chunk(pr3, lr3, mse, spos, stot, none);
    }

    // warp reduction (warp owns one row)
#pragma unroll
    for (int off = 16; off; off >>= 1) {
        mse  += __shfl_xor_sync(0xffffffffu, mse, off);
        spos += __shfl_xor_sync(0xffffffffu, spos, off);
        stot += __shfl_xor_sync(0xffffffffu, stot, off);
        none += __shfl_xor_sync(0xffffffffu, none, off);
    }

    __shared__ float s_mse[WARPS_PER_BLOCK];
    __shared__ float s_loss[WARPS_PER_BLOCK];
    __shared__ bool s_last;

    if (lane == 0) {
        float n1 = none;
        float n0 = (float)L_COLS - none;
        float sneg = stot - spos;
        float loss;
        if (n1 == 0.f) {
            loss = sneg * 0.36787944117144233f / fmaxf(n0, 1.f);  // e^{-1}*s_neg/n0
        } else if (n0 == 0.f) {
            loss = spos / n1;
        } else {
            loss = (spos * sneg) / (n1 * n0);
        }
        s_mse[warp] = mse;
        s_loss[warp] = loss;
    }
    __syncthreads();

    if (warp == 0 && lane < WARPS_PER_BLOCK) {
        float bm = s_mse[lane];
        float bl = s_loss[lane];
#pragma unroll
        for (int off = 4; off; off >>= 1) {
            bm += __shfl_xor_sync(0x000000ffu, bm, off);
            bl += __shfl_xor_sync(0x000000ffu, bl, off);
        }
        if (lane == 0) {
            g_part_mse[blockIdx.x] = bm;
            g_part_loss[blockIdx.x] = bl;
        }
    }

    // last-block final reduction (threadfence-reduction pattern)
    if (threadIdx.x == 0) {
        __threadfence();
        unsigned int prev = atomicAdd(&g_count, 1u);
        s_last = (prev == (unsigned)gridDim.x - 1u);
    }
    __syncthreads();

    if (s_last) {
        // 1024 partials per array; 256 threads -> one float4 each
        const float4* pm4 = reinterpret_cast<const float4*>(g_part_mse);
        const float4* pl4 = reinterpret_cast<const float4*>(g_part_loss);
        float4 vm = pm4[threadIdx.x];
        float4 vl = pl4[threadIdx.x];
        double dm = (double)vm.x + (double)vm.y + (double)vm.z + (double)vm.w;
        double dl = (double)vl.x + (double)vl.y + (double)vl.z + (double)vl.w;
#pragma unroll
        for (int off = 16; off; off >>= 1) {
            dm += __shfl_xor_sync(0xffffffffu, dm, off);
            dl += __shfl_xor_sync(0xffffffffu, dl, off);
        }
        __shared__ double sd_m[WARPS_PER_BLOCK];
        __shared__ double sd_l[WARPS_PER_BLOCK];
        if (lane == 0) {
            sd_m[warp] = dm;
            sd_l[warp] = dl;
        }
        __syncthreads();
        if (threadIdx.x == 0) {
            double tm = 0.0, tl = 0.0;
#pragma unroll
            for (int w = 0; w < WARPS_PER_BLOCK; ++w) {
                tm += sd_m[w];
                tl += sd_l[w];
            }
            out[0] = (float)(tm * (1.0 / ((double)B_ROWS * (double)L_COLS)) + tl);
            g_count = 0;  // reset for next graph replay
        }
    }
}

extern "C" void kernel_launch(void* const* d_in, const int* in_sizes, int n_in,
                              void* d_out, int out_size) {
    const float* pred  = (const float*)d_in[0];
    const float* label = (const float*)d_in[1];
    float* out = (float*)d_out;
    k_fused<<<GRID, THREADS>>>(pred, label, out);
}

// round 10
// speedup vs baseline: 1.4975x; 1.1800x over previous
#include <cuda_runtime.h>

// CorrelationMSELoss — B=8192 rows, L=1024 labels, single fused kernel.
// out = mean((pred-label)^2) + sum_rows(row_loss)
// R3-proven main loop; tail via two double atomic accumulators (no partials
// array, no last-block reduction).

static constexpr int B_ROWS = 8192;
static constexpr int L_COLS = 1024;
static constexpr int WARPS_PER_BLOCK = 8;
static constexpr int THREADS = WARPS_PER_BLOCK * 32;   // 256
static constexpr int GRID = B_ROWS / WARPS_PER_BLOCK;  // 1024 blocks, one wave

__device__ double g_sum_mse = 0.0;
__device__ double g_sum_loss = 0.0;
__device__ unsigned int g_count = 0;  // reset by last block each launch

__device__ __forceinline__ float ex2_approx(float x) {
    float r;
    asm("ex2.approx.ftz.f32 %0, %1;" : "=f"(r) : "f"(x));
    return r;
}

__device__ __forceinline__ void accum_chunk(float4 p, float4 l, float& mse,
                                            float& spos, float& stot, float& none) {
    constexpr float L2E = 1.4426950408889634f;  // log2(e)
    float pe[4] = {p.x, p.y, p.z, p.w};
    float le[4] = {l.x, l.y, l.z, l.w};
#pragma unroll
    for (int j = 0; j < 4; ++j) {
        float pv = pe[j], lv = le[j];
        float d = pv - lv;
        mse = fmaf(d, d, mse);
        float t = pv * L2E;
        float arg = fmaf(lv, -2.f * t, t);  // +t for lv=0, -t for lv=1
        float e = ex2_approx(arg);
        stot += e;
        spos = fmaf(lv, e, spos);
        none += lv;  // exact integer count
    }
}

__global__ __launch_bounds__(THREADS) void k_fused(const float* __restrict__ pred,
                                                   const float* __restrict__ label,
                                                   float* __restrict__ out) {
    const int lane = threadIdx.x & 31;
    const int warp = threadIdx.x >> 5;
    const int row = blockIdx.x * WARPS_PER_BLOCK + warp;

    const float4* p4 = reinterpret_cast<const float4*>(pred) + (long)row * (L_COLS / 4) + lane;
    const float4* l4 = reinterpret_cast<const float4*>(label) + (long)row * (L_COLS / 4) + lane;

    float mse = 0.f, spos = 0.f, stot = 0.f, none = 0.f;

#pragma unroll
    for (int i = 0; i < L_COLS / 4 / 32; ++i) {  // 8 iterations
        float4 p = __ldg(p4 + i * 32);
        float4 l = __ldg(l4 + i * 32);
        accum_chunk(p, l, mse, spos, stot, none);
    }

    // warp reduction (warp owns one row)
#pragma unroll
    for (int off = 16; off; off >>= 1) {
        mse  += __shfl_xor_sync(0xffffffffu, mse, off);
        spos += __shfl_xor_sync(0xffffffffu, spos, off);
        stot += __shfl_xor_sync(0xffffffffu, stot, off);
        none += __shfl_xor_sync(0xffffffffu, none, off);
    }

    __shared__ float s_mse[WARPS_PER_BLOCK];
    __shared__ float s_loss[WARPS_PER_BLOCK];

    if (lane == 0) {
        float n1 = none;
        float n0 = (float)L_COLS - none;
        float sneg = stot - spos;
        float loss;
        if (n1 == 0.f) {
            loss = sneg * 0.36787944117144233f / fmaxf(n0, 1.f);  // e^{-1}*s_neg/n0
        } else if (n0 == 0.f) {
            loss = spos / n1;
        } else {
            loss = (spos * sneg) / (n1 * n0);
        }
        s_mse[warp] = mse;
        s_loss[warp] = loss;
    }
    __syncthreads();

    // warp 0 folds the 8 per-warp results; lane 0 does the global accumulate
    if (warp == 0) {
        float bm = (lane < WARPS_PER_BLOCK) ? s_mse[lane] : 0.f;
        float bl = (lane < WARPS_PER_BLOCK) ? s_loss[lane] : 0.f;
#pragma unroll
        for (int off = 4; off; off >>= 1) {
            bm += __shfl_xor_sync(0xffffffffu, bm, off);
            bl += __shfl_xor_sync(0xffffffffu, bl, off);
        }
        if (lane == 0) {
            atomicAdd(&g_sum_mse, (double)bm);
            atomicAdd(&g_sum_loss, (double)bl);
            __threadfence();
            unsigned int prev = atomicAdd(&g_count, 1u);
            if (prev == (unsigned)GRID - 1u) {
                // last block: all other blocks' sums are visible (fence-before-
                // increment on their side, atomic read on ours)
                __threadfence();
                double tm = g_sum_mse;
                double tl = g_sum_loss;
                out[0] = (float)(tm * (1.0 / ((double)B_ROWS * (double)L_COLS)) + tl);
                // reset for next graph replay (stream-ordered: next launch
                // cannot begin until this kernel fully retires)
                g_sum_mse = 0.0;
                g_sum_loss = 0.0;
                g_count = 0;
            }
        }
    }
}

extern "C" void kernel_launch(void* const* d_in, const int* in_sizes, int n_in,
                              void* d_out, int out_size) {
    const float* pred  = (const float*)d_in[0];
    const float* label = (const float*)d_in[1];
    float* out = (float*)d_out;
    k_fused<<<GRID, THREADS>>>(pred, label, out);
}